// round 16
// baseline (speedup 1.0000x reference)
#include <cuda_runtime.h>
#include <math.h>
#include <float.h>

#define NPTS 8192
#define KNN  20

// ------------------------- scratch (__device__ globals, no allocation) ------
__device__ float g_D[(size_t)NPTS * NPTS];   // 256 MB dist matrix
__device__ float g_x2[NPTS];
__device__ int   g_idx[NPTS * KNN];
__device__ float g_cat[NPTS * 420];          // x1|x2|x3 concatenated (60|120|240)
__device__ float g_h1[NPTS * 1024];
__device__ float g_h2[NPTS * 256];
__device__ float g_h3[NPTS * 128];

// ------------------------- packed f32x2 FMA ---------------------------------
__device__ __forceinline__ unsigned long long ffma2(
    unsigned long long a, unsigned long long b, unsigned long long c) {
    unsigned long long d;
    asm("fma.rn.f32x2 %0, %1, %2, %3;" : "=l"(d) : "l"(a), "l"(b), "l"(c));
    return d;
}
__device__ __forceinline__ unsigned long long pack2(float x) {
    unsigned long long d;
    asm("mov.b64 %0, {%1, %2};" : "=l"(d) : "f"(x), "f"(x));
    return d;
}
__device__ __forceinline__ void unpack2(unsigned long long p, float& lo, float& hi) {
    asm("mov.b64 {%0, %1}, %2;" : "=f"(lo), "=f"(hi) : "l"(p));
}

// ------------------------- cp.async helpers ---------------------------------
// Register-free gmem->smem staging: frees the prefetch registers in the
// double-buffered GEMM mainloops (arithmetic untouched -> bitwise neutral).
__device__ __forceinline__ void cp4(unsigned int s, const float* g) {
    asm volatile("cp.async.ca.shared.global [%0], [%1], 4;\n" :: "r"(s), "l"(g));
}
#define CP_COMMIT() asm volatile("cp.async.commit_group;\n" ::: "memory")
#define CP_WAIT0()  asm volatile("cp.async.wait_group 0;\n" ::: "memory")

// ------------------------- squared norms (layer 1 only) ---------------------
__global__ void sqnorm_seq_kernel(const float* __restrict__ X, int ld, int C,
                                  float* __restrict__ x2) {
    int i = blockIdx.x * blockDim.x + threadIdx.x;
    if (i >= NPTS) return;
    const float* r = X + (size_t)i * ld;
    float s = 0.f;
    for (int c = 0; c < C; ++c)
        s = __fadd_rn(s, __fmul_rn(r[c], r[c]));
    x2[i] = s;
}

#define BM 128
#define BN 128

// triangle decode: linear block id -> (bx, by), by <= bx
__device__ __forceinline__ void tri_decode(int t, int& bx, int& by) {
    bx = (int)((sqrtf(8.f * (float)t + 1.f) - 1.f) * 0.5f);
    while ((bx + 1) * (bx + 2) / 2 <= t) ++bx;
    while (bx * (bx + 1) / 2 > t) --bx;
    by = t - bx * (bx + 1) / 2;
}

// epilogue + symmetric dual store (scalar chain, unchanged)
__device__ __forceinline__ void dist_store(float acc[8][8],
                                           const float* __restrict__ x2v,
                                           float* __restrict__ D,
                                           int i0, int j0, int tx, int ty,
                                           bool offdiag) {
    float res[8][8];
#pragma unroll
    for (int u = 0; u < 8; ++u) {
        int i = i0 + ty * 8 + u;
#pragma unroll
        for (int v = 0; v < 8; ++v) {
            int j = j0 + tx * 8 + v;
            float s = __fadd_rn(x2v[i], x2v[j]);
            res[u][v] = __fsub_rn(s, __fmul_rn(2.f, acc[u][v]));
        }
    }
#pragma unroll
    for (int u = 0; u < 8; ++u) {
        int i = i0 + ty * 8 + u;
        *(float4*)&D[(size_t)i * NPTS + j0 + tx * 8]     = *(float4*)&res[u][0];
        *(float4*)&D[(size_t)i * NPTS + j0 + tx * 8 + 4] = *(float4*)&res[u][4];
    }
    if (offdiag) {
#pragma unroll
        for (int v = 0; v < 8; ++v) {
            int j = j0 + tx * 8 + v;
            float4 p0 = make_float4(res[0][v], res[1][v], res[2][v], res[3][v]);
            float4 p1 = make_float4(res[4][v], res[5][v], res[6][v], res[7][v]);
            *(float4*)&D[(size_t)j * NPTS + i0 + ty * 8]     = p0;
            *(float4*)&D[(size_t)j * NPTS + i0 + ty * 8 + 4] = p1;
        }
    }
}

// ------------------------- fused kNN for C=3 (no D matrix) ------------------
__global__ __launch_bounds__(1024, 1) void knn3_kernel(
    const float* __restrict__ X,
    const float* __restrict__ x2v,
    int* __restrict__ out) {
    extern __shared__ float sm[];
    float* A0 = sm;
    float* A1 = sm + NPTS;
    float* A2 = sm + 2 * NPTS;
    float* X2 = sm + 3 * NPTS;
    float* sd = X2 + NPTS;                     // [32][KNN]
    int*   si = (int*)(sd + 32 * KNN);         // [32][KNN]

    const int tid = threadIdx.x;
    for (int j = tid; j < NPTS; j += 1024) {
        const float* p = X + (size_t)j * 3;
        A0[j] = p[0]; A1[j] = p[1]; A2[j] = p[2];
        X2[j] = x2v[j];
    }
    __syncthreads();

    const int lane = tid & 31;
    const int w    = tid >> 5;
    const int row  = blockIdx.x * 32 + w;

    const float a0 = A0[row], a1 = A1[row], a2 = A2[row];
    const float xi = X2[row];

    float* wd = sd + w * KNN;
    int*   wi = si + w * KNN;
    if (lane < KNN) { wd[lane] = FLT_MAX; wi[lane] = 0x7fffffff; }
    __syncwarp();

    float thresh = FLT_MAX;
    for (int base = 0; base < NPTS; base += 128) {
        float dv[4];
#pragma unroll
        for (int q = 0; q < 4; ++q) {
            const int j = base + q * 32 + lane;
            float acc = fmaf(a0, A0[j], 0.f);
            acc = fmaf(a1, A1[j], acc);
            acc = fmaf(a2, A2[j], acc);
            dv[q] = __fsub_rn(__fadd_rn(xi, X2[j]), __fmul_rn(2.f, acc));
        }
#pragma unroll
        for (int q = 0; q < 4; ++q) {
            float d = dv[q];
            unsigned m = __ballot_sync(0xffffffffu, d < thresh);
            while (m) {
                int src = __ffs(m) - 1;
                m &= m - 1;
                float dc = __shfl_sync(0xffffffffu, d, src);
                int   jc = base + q * 32 + src;
                if (lane == 0) {
                    if (dc < wd[KNN - 1]) {
                        int p = KNN - 1;
                        while (p > 0 && wd[p - 1] > dc) {
                            wd[p] = wd[p - 1];
                            wi[p] = wi[p - 1];
                            --p;
                        }
                        wd[p] = dc;
                        wi[p] = jc;
                    }
                }
                __syncwarp();
                thresh = wd[KNN - 1];
            }
        }
    }
    if (lane < KNN) out[row * KNN + lane] = wi[lane];
}

// ------------------------- symmetric pairwise distance ----------------------
// BK=20 (divides 60/120), double-buffered via cp.async (no staging regs).
template <int K>
__global__ __launch_bounds__(256, 2) void dist_sym_kernel(
    const float* __restrict__ X, int ld,
    const float* __restrict__ x2v,
    float* __restrict__ D) {
    const int BKT = 20;
    __shared__ float As[2][BKT][BM + 4];
    __shared__ float Bs[2][BKT][BN + 4];

    int bx, by;
    tri_decode(blockIdx.x, bx, by);
    const int i0 = bx * BM, j0 = by * BN;
    const int tid = threadIdx.x;
    const int tx = tid & 15, ty = tid >> 4;

    const unsigned int baseA = (unsigned int)__cvta_generic_to_shared(&As[0][0][0]);
    const unsigned int baseB = (unsigned int)__cvta_generic_to_shared(&Bs[0][0][0]);
    const unsigned int bufStride = BKT * (BM + 4) * 4;

    unsigned long long acc2[8][4];
#pragma unroll
    for (int u = 0; u < 8; ++u)
#pragma unroll
        for (int p = 0; p < 4; ++p) acc2[u][p] = 0ull;

    // tile 0 via cp.async
#pragma unroll
    for (int p = 0; p < 10; ++p) {
        int e = tid + 256 * p, r = e / BKT, c = e - r * BKT;
        unsigned int off = (unsigned int)(c * (BM + 4) + r) * 4;
        cp4(baseA + off, X + (size_t)(i0 + r) * ld + c);
        cp4(baseB + off, X + (size_t)(j0 + r) * ld + c);
    }
    CP_COMMIT(); CP_WAIT0(); __syncthreads();

    const int nt = K / BKT;
    int buf = 0;
    for (int t = 1; t < nt; ++t) {
        const int kk = t * BKT;
        const unsigned int dst = (unsigned int)(buf ^ 1) * bufStride;
#pragma unroll
        for (int p = 0; p < 10; ++p) {
            int e = tid + 256 * p, r = e / BKT, c = e - r * BKT;
            unsigned int off = dst + (unsigned int)(c * (BM + 4) + r) * 4;
            cp4(baseA + off, X + (size_t)(i0 + r) * ld + kk + c);
            cp4(baseB + off, X + (size_t)(j0 + r) * ld + kk + c);
        }
        CP_COMMIT();
#pragma unroll
        for (int k = 0; k < BKT; ++k) {
            float a[8];
            *(float4*)&a[0] = *(const float4*)&As[buf][k][ty * 8];
            *(float4*)&a[4] = *(const float4*)&As[buf][k][ty * 8 + 4];
            ulonglong2 t0 = *(const ulonglong2*)&Bs[buf][k][tx * 8];
            ulonglong2 t1 = *(const ulonglong2*)&Bs[buf][k][tx * 8 + 4];
            unsigned long long b2[4] = {t0.x, t0.y, t1.x, t1.y};
#pragma unroll
            for (int u = 0; u < 8; ++u) {
                unsigned long long a2 = pack2(a[u]);
#pragma unroll
                for (int p = 0; p < 4; ++p)
                    acc2[u][p] = ffma2(a2, b2[p], acc2[u][p]);
            }
        }
        CP_WAIT0();
        __syncthreads();
        buf ^= 1;
    }
#pragma unroll
    for (int k = 0; k < BKT; ++k) {
        float a[8];
        *(float4*)&a[0] = *(const float4*)&As[buf][k][ty * 8];
        *(float4*)&a[4] = *(const float4*)&As[buf][k][ty * 8 + 4];
        ulonglong2 t0 = *(const ulonglong2*)&Bs[buf][k][tx * 8];
        ulonglong2 t1 = *(const ulonglong2*)&Bs[buf][k][tx * 8 + 4];
        unsigned long long b2[4] = {t0.x, t0.y, t1.x, t1.y};
#pragma unroll
        for (int u = 0; u < 8; ++u) {
            unsigned long long a2 = pack2(a[u]);
#pragma unroll
            for (int p = 0; p < 4; ++p)
                acc2[u][p] = ffma2(a2, b2[p], acc2[u][p]);
        }
    }

    float acc[8][8];
#pragma unroll
    for (int u = 0; u < 8; ++u)
#pragma unroll
        for (int p = 0; p < 4; ++p)
            unpack2(acc2[u][p], acc[u][2 * p], acc[u][2 * p + 1]);

    dist_store(acc, x2v, D, i0, j0, tx, ty, bx != by);
}

// ------------------------- GEMM 128x128, BK=20 (lin1: K=420 exact) ----------
__global__ __launch_bounds__(256, 2) void gemm128_kernel(
    const float* __restrict__ A, int lda,
    const float* __restrict__ B, int ldb,
    const float* __restrict__ bias,
    float* __restrict__ Cout, int ldc,
    int N, int K) {
    const int BKT = 20;
    __shared__ float As[2][BKT][BM + 4];
    __shared__ float Bs[2][BKT][BN + 4];

    const int tid = threadIdx.x;
    const int tx = tid & 15, ty = tid >> 4;
    const int i0 = blockIdx.y * BM;
    const int j0 = blockIdx.x * BN;

    const unsigned int baseA = (unsigned int)__cvta_generic_to_shared(&As[0][0][0]);
    const unsigned int baseB = (unsigned int)__cvta_generic_to_shared(&Bs[0][0][0]);
    const unsigned int strA = BKT * (BM + 4) * 4;
    const unsigned int strB = BKT * (BN + 4) * 4;

    unsigned long long acc2[8][4];
#pragma unroll
    for (int u = 0; u < 8; ++u)
#pragma unroll
        for (int p = 0; p < 4; ++p) acc2[u][p] = 0ull;

#pragma unroll
    for (int p = 0; p < 10; ++p) {
        int e = tid + 256 * p;
        { int r = e / BKT, c = e - r * BKT;
          cp4(baseA + (unsigned int)(c * (BM + 4) + r) * 4,
              A + (size_t)(i0 + r) * lda + c); }
        { int r = e >> 7, c = e & 127;
          cp4(baseB + (unsigned int)(r * (BN + 4) + c) * 4,
              B + (size_t)r * ldb + j0 + c); }
    }
    CP_COMMIT(); CP_WAIT0(); __syncthreads();

    const int nt = K / BKT;      // 420 / 20 = 21
    int buf = 0;
    for (int t = 1; t < nt; ++t) {
        const int kk = t * BKT;
        const unsigned int dA = (unsigned int)(buf ^ 1) * strA;
        const unsigned int dB = (unsigned int)(buf ^ 1) * strB;
#pragma unroll
        for (int p = 0; p < 10; ++p) {
            int e = tid + 256 * p;
            { int r = e / BKT, c = e - r * BKT;
              cp4(baseA + dA + (unsigned int)(c * (BM + 4) + r) * 4,
                  A + (size_t)(i0 + r) * lda + kk + c); }
            { int r = e >> 7, c = e & 127;
              cp4(baseB + dB + (unsigned int)(r * (BN + 4) + c) * 4,
                  B + (size_t)(kk + r) * ldb + j0 + c); }
        }
        CP_COMMIT();
#pragma unroll
        for (int k = 0; k < BKT; ++k) {
            float a[8];
            *(float4*)&a[0] = *(const float4*)&As[buf][k][ty * 8];
            *(float4*)&a[4] = *(const float4*)&As[buf][k][ty * 8 + 4];
            ulonglong2 t0 = *(const ulonglong2*)&Bs[buf][k][tx * 8];
            ulonglong2 t1 = *(const ulonglong2*)&Bs[buf][k][tx * 8 + 4];
            unsigned long long b2[4] = {t0.x, t0.y, t1.x, t1.y};
#pragma unroll
            for (int u = 0; u < 8; ++u) {
                unsigned long long a2 = pack2(a[u]);
#pragma unroll
                for (int p = 0; p < 4; ++p)
                    acc2[u][p] = ffma2(a2, b2[p], acc2[u][p]);
            }
        }
        CP_WAIT0();
        __syncthreads();
        buf ^= 1;
    }
#pragma unroll
    for (int k = 0; k < BKT; ++k) {
        float a[8];
        *(float4*)&a[0] = *(const float4*)&As[buf][k][ty * 8];
        *(float4*)&a[4] = *(const float4*)&As[buf][k][ty * 8 + 4];
        ulonglong2 t0 = *(const ulonglong2*)&Bs[buf][k][tx * 8];
        ulonglong2 t1 = *(const ulonglong2*)&Bs[buf][k][tx * 8 + 4];
        unsigned long long b2[4] = {t0.x, t0.y, t1.x, t1.y};
#pragma unroll
        for (int u = 0; u < 8; ++u) {
            unsigned long long a2 = pack2(a[u]);
#pragma unroll
            for (int p = 0; p < 4; ++p)
                acc2[u][p] = ffma2(a2, b2[p], acc2[u][p]);
        }
    }

    float acc[8][8];
#pragma unroll
    for (int u = 0; u < 8; ++u)
#pragma unroll
        for (int p = 0; p < 4; ++p)
            unpack2(acc2[u][p], acc[u][2 * p], acc[u][2 * p + 1]);

#pragma unroll
    for (int u = 0; u < 8; ++u) {
        int i = i0 + ty * 8 + u;
#pragma unroll
        for (int v = 0; v < 8; ++v)
            Cout[(size_t)i * ldc + j0 + tx * 8 + v] =
                fmaxf(__fadd_rn(acc[u][v], bias[j0 + tx * 8 + v]), 0.f);
    }
}

// ------------------------- GEMM 64x128, BK=16 (wa, wb) ----------------------
__global__ __launch_bounds__(256, 3) void gemm64_kernel(
    const float* __restrict__ A, int lda,
    const float* __restrict__ B, int ldb,
    const float* __restrict__ bias,
    float* __restrict__ Cout, int ldc,
    int N, int K) {
    const int BKT = 16;
    __shared__ float As[2][BKT][64 + 4];
    __shared__ float Bs[2][BKT][128 + 4];

    const int tid = threadIdx.x;
    const int tx = tid & 15, ty = tid >> 4;
    const int i0 = blockIdx.y * 64;
    const int j0 = blockIdx.x * 128;

    const unsigned int baseA = (unsigned int)__cvta_generic_to_shared(&As[0][0][0]);
    const unsigned int baseB = (unsigned int)__cvta_generic_to_shared(&Bs[0][0][0]);
    const unsigned int strA = BKT * 68 * 4;
    const unsigned int strB = BKT * 132 * 4;

    unsigned long long acc2[4][4];
#pragma unroll
    for (int u = 0; u < 4; ++u)
#pragma unroll
        for (int p = 0; p < 4; ++p) acc2[u][p] = 0ull;

#pragma unroll
    for (int p = 0; p < 4; ++p) {
        int e = tid + 256 * p, r = e >> 4, c = e & 15;
        cp4(baseA + (unsigned int)(c * 68 + r) * 4, A + (size_t)(i0 + r) * lda + c);
    }
#pragma unroll
    for (int p = 0; p < 8; ++p) {
        int e = tid + 256 * p, r = e >> 7, c = e & 127;
        cp4(baseB + (unsigned int)(r * 132 + c) * 4, B + (size_t)r * ldb + j0 + c);
    }
    CP_COMMIT(); CP_WAIT0(); __syncthreads();

    const int nt = K / BKT;
    int buf = 0;
    for (int t = 1; t < nt; ++t) {
        const int kk = t * BKT;
        const unsigned int dA = (unsigned int)(buf ^ 1) * strA;
        const unsigned int dB = (unsigned int)(buf ^ 1) * strB;
#pragma unroll
        for (int p = 0; p < 4; ++p) {
            int e = tid + 256 * p, r = e >> 4, c = e & 15;
            cp4(baseA + dA + (unsigned int)(c * 68 + r) * 4,
                A + (size_t)(i0 + r) * lda + kk + c);
        }
#pragma unroll
        for (int p = 0; p < 8; ++p) {
            int e = tid + 256 * p, r = e >> 7, c = e & 127;
            cp4(baseB + dB + (unsigned int)(r * 132 + c) * 4,
                B + (size_t)(kk + r) * ldb + j0 + c);
        }
        CP_COMMIT();
#pragma unroll
        for (int k = 0; k < BKT; ++k) {
            float a[4];
            *(float4*)&a[0] = *(const float4*)&As[buf][k][ty * 4];
            ulonglong2 t0 = *(const ulonglong2*)&Bs[buf][k][tx * 8];
            ulonglong2 t1 = *(const ulonglong2*)&Bs[buf][k][tx * 8 + 4];
            unsigned long long b2[4] = {t0.x, t0.y, t1.x, t1.y};
#pragma unroll
            for (int u = 0; u < 4; ++u) {
                unsigned long long a2 = pack2(a[u]);
#pragma unroll
                for (int p = 0; p < 4; ++p)
                    acc2[u][p] = ffma2(a2, b2[p], acc2[u][p]);
            }
        }
        CP_WAIT0();
        __syncthreads();
        buf ^= 1;
    }
#pragma unroll
    for (int k = 0; k < BKT; ++k) {
        float a[4];
        *(float4*)&a[0] = *(const float4*)&As[buf][k][ty * 4];
        ulonglong2 t0 = *(const ulonglong2*)&Bs[buf][k][tx * 8];
        ulonglong2 t1 = *(const ulonglong2*)&Bs[buf][k][tx * 8 + 4];
        unsigned long long b2[4] = {t0.x, t0.y, t1.x, t1.y};
#pragma unroll
        for (int u = 0; u < 4; ++u) {
            unsigned long long a2 = pack2(a[u]);
#pragma unroll
            for (int p = 0; p < 4; ++p)
                acc2[u][p] = ffma2(a2, b2[p], acc2[u][p]);
        }
    }

    float acc[4][8];
#pragma unroll
    for (int u = 0; u < 4; ++u)
#pragma unroll
        for (int p = 0; p < 4; ++p)
            unpack2(acc2[u][p], acc[u][2 * p], acc[u][2 * p + 1]);

#pragma unroll
    for (int u = 0; u < 4; ++u) {
        int i = i0 + ty * 4 + u;
#pragma unroll
        for (int v = 0; v < 8; ++v) {
            int j = j0 + tx * 8 + v;
            if (j < N)
                Cout[(size_t)i * ldc + j] =
                    fmaxf(__fadd_rn(acc[u][v], bias[j]), 0.f);
        }
    }
}

// ------------------------- top-20 selection (warp per row, 4x unrolled) -----
__global__ void topk_kernel(const float* __restrict__ D, int* __restrict__ out) {
    __shared__ float sd[8][KNN];
    __shared__ int   si[8][KNN];

    const int lane = threadIdx.x & 31;
    const int wloc = threadIdx.x >> 5;
    const int row  = (blockIdx.x * blockDim.x + threadIdx.x) >> 5;

    if (lane < KNN) { sd[wloc][lane] = FLT_MAX; si[wloc][lane] = 0x7fffffff; }
    __syncwarp();

    const float* r = D + (size_t)row * NPTS;
    float* wd = sd[wloc];
    int*   wi = si[wloc];
    float thresh = FLT_MAX;

    for (int base = 0; base < NPTS; base += 128) {
        float dv[4];
        dv[0] = r[base + lane];
        dv[1] = r[base + 32 + lane];
        dv[2] = r[base + 64 + lane];
        dv[3] = r[base + 96 + lane];
#pragma unroll
        for (int q = 0; q < 4; ++q) {
            float d = dv[q];
            unsigned m = __ballot_sync(0xffffffffu, d < thresh);
            while (m) {
                int src = __ffs(m) - 1;
                m &= m - 1;
                float dc = __shfl_sync(0xffffffffu, d, src);
                int   jc = base + q * 32 + src;
                if (lane == 0) {
                    if (dc < wd[KNN - 1]) {
                        int p = KNN - 1;
                        while (p > 0 && wd[p - 1] > dc) {
                            wd[p] = wd[p - 1];
                            wi[p] = wi[p - 1];
                            --p;
                        }
                        wd[p] = dc;
                        wi[p] = jc;
                    }
                }
                __syncwarp();
                thresh = wd[KNN - 1];
            }
        }
    }
    if (lane < KNN) out[row * KNN + lane] = wi[lane];
}

// ------------------------- erosion EdgeConv (+ fused next-layer x2) ---------
__global__ void erode_kernel(const float* __restrict__ Xin, int ldin,
                             const int* __restrict__ idx,
                             const float* __restrict__ w,
                             float* __restrict__ out, int ldout,
                             int F, int C,
                             float* __restrict__ x2out) {
    __shared__ float nb[KNN * 120];    // max C = 120
    __shared__ float ov[240];          // max F*C = 240
    const int i = blockIdx.x;
    const int* ip = idx + i * KNN;

    for (int e = threadIdx.x; e < KNN * C; e += blockDim.x) {
        int k = e / C, c = e - k * C;
        nb[e] = Xin[(size_t)ip[k] * ldin + c];
    }
    __syncthreads();

    const int FC = F * C;
    for (int e = threadIdx.x; e < FC; e += blockDim.x) {
        int f = e / C, c = e - f * C;
        float mn = FLT_MAX;
        const float* wf = w + (size_t)f * KNN * C + c;
#pragma unroll 4
        for (int k = 0; k < KNN; ++k)
            mn = fminf(mn, __fsub_rn(nb[k * C + c], wf[k * C]));
        out[(size_t)i * ldout + e] = mn;
        ov[e] = mn;
    }

    if (x2out) {
        __syncthreads();
        if (threadIdx.x < 32) {
            const int lane = threadIdx.x;
            float s = 0.f;
            for (int c = lane; c < FC; c += 32)
                s = __fadd_rn(s, __fmul_rn(ov[c], ov[c]));
#pragma unroll
            for (int off = 16; off > 0; off >>= 1)
                s = __fadd_rn(s, __shfl_down_sync(0xffffffffu, s, off));
            if (lane == 0) x2out[i] = s;
        }
    }
}

// ------------------------- final linear + log_softmax -----------------------
__global__ void head_kernel(const float* __restrict__ H,
                            const float* __restrict__ wo,
                            const float* __restrict__ bo,
                            float* __restrict__ out) {
    __shared__ float h[128];
    __shared__ float lg[40];
    __shared__ float s_lse;
    const int i = blockIdx.x;
    const int t = threadIdx.x;              // 128 threads

    h[t] = H[(size_t)i * 128 + t];
    __syncthreads();

    if (t < 40) {
        float s = 0.f;
#pragma unroll 8
        for (int k = 0; k < 128; ++k) s = fmaf(h[k], wo[k * 40 + t], s);
        lg[t] = __fadd_rn(s, bo[t]);
    }
    __syncthreads();

    if (t == 0) {
        float m = -FLT_MAX;
        for (int n = 0; n < 40; ++n) m = fmaxf(m, lg[n]);
        float s = 0.f;
        for (int n = 0; n < 40; ++n) s = __fadd_rn(s, expf(__fsub_rn(lg[n], m)));
        s_lse = __fadd_rn(m, logf(s));
    }
    __syncthreads();

    if (t < 40) out[(size_t)i * 40 + t] = __fsub_rn(lg[t], s_lse);
}

// ------------------------- launch sequence ----------------------------------
extern "C" void kernel_launch(void* const* d_in, const int* in_sizes, int n_in,
                              void* d_out, int out_size) {
    const float* x      = (const float*)d_in[0];
    const float* w1     = (const float*)d_in[1];
    const float* w2     = (const float*)d_in[2];
    const float* w3     = (const float*)d_in[3];
    const float* lin1_w = (const float*)d_in[4];
    const float* lin1_b = (const float*)d_in[5];
    const float* wa     = (const float*)d_in[6];
    const float* ba     = (const float*)d_in[7];
    const float* wb     = (const float*)d_in[8];
    const float* bb     = (const float*)d_in[9];
    const float* wo     = (const float*)d_in[10];
    const float* bo     = (const float*)d_in[11];
    float* out = (float*)d_out;

    float *D, *x2, *cat, *h1, *h2, *h3;
    int* idxp;
    cudaGetSymbolAddress((void**)&D,   g_D);
    cudaGetSymbolAddress((void**)&x2,  g_x2);
    cudaGetSymbolAddress((void**)&idxp,g_idx);
    cudaGetSymbolAddress((void**)&cat, g_cat);
    cudaGetSymbolAddress((void**)&h1,  g_h1);
    cudaGetSymbolAddress((void**)&h2,  g_h2);
    cudaGetSymbolAddress((void**)&h3,  g_h3);

    const int NB = NPTS / BM;                 // 64 tiles per dim
    const int NTRI = NB * (NB + 1) / 2;       // 2080 lower-triangle blocks

    const int smem_knn3 = (4 * NPTS + 32 * KNN) * (int)sizeof(float)
                        + 32 * KNN * (int)sizeof(int);   // ~133 KB
    cudaFuncSetAttribute(knn3_kernel,
                         cudaFuncAttributeMaxDynamicSharedMemorySize, smem_knn3);

    // ---- layer 1: kNN on x (C=3) fused, erode (+x2 for layer 2)
    sqnorm_seq_kernel<<<32, 256>>>(x, 3, 3, x2);
    knn3_kernel<<<NPTS / 32, 1024, smem_knn3>>>(x, x2, idxp);
    erode_kernel<<<NPTS, 128>>>(x, 3, idxp, w1, cat, 420, 20, 3, x2);

    // ---- layer 2: kNN on x1 (C=60), erode (+x2 for layer 3)
    dist_sym_kernel<60><<<NTRI, 256>>>(cat, 420, x2, D);
    topk_kernel<<<NPTS / 8, 256>>>(D, idxp);
    erode_kernel<<<NPTS, 128>>>(cat, 420, idxp, w2, cat + 60, 420, 2, 60, x2);

    // ---- layer 3: kNN on x2 (C=120), erode
    dist_sym_kernel<120><<<NTRI, 256>>>(cat + 60, 420, x2, D);
    topk_kernel<<<NPTS / 8, 256>>>(D, idxp);
    erode_kernel<<<NPTS, 128>>>(cat + 60, 420, idxp, w3, cat + 180, 420, 2, 120,
                                nullptr);

    // ---- MLP head
    gemm128_kernel<<<dim3(1024 / BN, NPTS / BM), 256>>>(
        cat, 420, lin1_w, 1024, lin1_b, h1, 1024, 1024, 420);
    gemm64_kernel<<<dim3(2, NPTS / 64), 256>>>(
        h1, 1024, wa, 256, ba, h2, 256, 256, 1024);
    gemm64_kernel<<<dim3(1, NPTS / 64), 256>>>(
        h2, 256, wb, 128, bb, h3, 128, 128, 256);

    head_kernel<<<NPTS, 128>>>(h3, wo, bo, out);
}